// round 1
// baseline (speedup 1.0000x reference)
#include <cuda_runtime.h>
#include <math.h>

// Scratch (allocation-free requirement): nbw and h, each (B,C,F) = 262144 floats
__device__ float g_nbw[256 * 4 * 256];
__device__ float g_h[256 * 4 * 256];

#define Bsz 256
#define Cc  4
#define Nn  64
#define Ff  256

// ---------------------------------------------------------------------------
// K1: per-batch attention: s1, s2, softmax w, then nbw[b,c,f] = sum_n w[n]*nbr
// grid = 256 (one block per b), 256 threads
// ---------------------------------------------------------------------------
__global__ __launch_bounds__(256) void k_attn(
    const float* __restrict__ x, const float* __restrict__ nbr,
    const float* __restrict__ Wa1, const float* __restrict__ Wa2,
    float* __restrict__ nbw)
{
    int b = blockIdx.x;
    int t = threadIdx.x;
    __shared__ float w2s_s[256];
    __shared__ float red[256];
    __shared__ float s2_s[64];
    __shared__ float w_s[64];
    __shared__ float s1_s;

    // per-f channel sums
    float xs  = x[(b*Cc+0)*Ff+t] + x[(b*Cc+1)*Ff+t] + x[(b*Cc+2)*Ff+t] + x[(b*Cc+3)*Ff+t];
    float w1s = Wa1[t] + Wa1[256+t] + Wa1[512+t] + Wa1[768+t];
    float w2s = Wa2[t] + Wa2[256+t] + Wa2[512+t] + Wa2[768+t];
    w2s_s[t] = w2s;
    red[t]   = xs * w1s;
    __syncthreads();
    // block reduce -> s1
    for (int off = 128; off > 0; off >>= 1) {
        if (t < off) red[t] += red[t + off];
        __syncthreads();
    }
    if (t == 0) s1_s = red[0];

    // s2[n]: 8 warps x 8 n each; warp reduces 1024 elems
    int warp = t >> 5, lane = t & 31;
    const float* nb_b = nbr + (size_t)b * Nn * Cc * Ff;
    for (int n = warp; n < Nn; n += 8) {
        const float* p = nb_b + (size_t)n * (Cc * Ff);
        float acc = 0.f;
        #pragma unroll 8
        for (int i = lane; i < Cc * Ff; i += 32) acc += p[i] * w2s_s[i & 255];
        #pragma unroll
        for (int o = 16; o > 0; o >>= 1) acc += __shfl_down_sync(0xffffffffu, acc, o);
        if (lane == 0) s2_s[n] = acc;
    }
    __syncthreads();

    // softmax over n of s1*s2[n] (serial on thread 0; 64 elems)
    if (t == 0) {
        float s1 = s1_s;
        float m = -1e30f;
        for (int n = 0; n < Nn; n++) {
            float v = s1 * s2_s[n];
            s2_s[n] = v;
            m = fmaxf(m, v);
        }
        float sum = 0.f;
        for (int n = 0; n < Nn; n++) {
            float e = expf(s2_s[n] - m);
            w_s[n] = e;
            sum += e;
        }
        float isum = 1.f / sum;
        for (int n = 0; n < Nn; n++) w_s[n] *= isum;
    }
    __syncthreads();

    // nbw[b,c,t] = sum_n w[n] * nbr[b,n,c,t]   (2nd read of nbr[b] -> L2 hit)
    for (int c = 0; c < Cc; c++) {
        const float* p = nb_b + c * Ff + t;
        float acc = 0.f;
        #pragma unroll 8
        for (int n = 0; n < Nn; n++) acc += w_s[n] * p[(size_t)n * (Cc * Ff)];
        nbw[(b*Cc + c)*Ff + t] = acc;
    }
}

// ---------------------------------------------------------------------------
// K2: per (b,c): adj tile (256x256) + h.  Rank-2 symmetric structure:
//   g[x,y] = sgnroot(a[x]*v[y] + a[y]*v[x])  (symmetric)
//   d[y]   = sum_x |g[x,y]|  (== row sum, so thread-local register loop)
//   adj[x,y] = g[x,y] / (d[y]+1e-7);  h[x] = sum_y adj[x,y]*a[y]
// grid = 1024 (b*C+c), 256 threads (thread = its column/row index)
// ---------------------------------------------------------------------------
__global__ __launch_bounds__(256) void k_adj(
    const float* __restrict__ x, const float* __restrict__ nbw,
    float* __restrict__ adj, float* __restrict__ h)
{
    int bc = blockIdx.x;
    int t  = threadIdx.x;
    __shared__ float a_s[256];
    __shared__ float v_s[256];
    __shared__ float e_s[256];

    float a = x[bc*Ff + t];
    float v = nbw[bc*Ff + t];
    a_s[t] = a;
    v_s[t] = v;
    __syncthreads();

    // pass 1: d[t] = sum_y |g[t,y]|
    float d = 0.f;
    #pragma unroll 8
    for (int y = 0; y < 256; y++) {
        float f  = a * v_s[y] + a_s[y] * v;
        float s  = sqrtf(fmaxf(fabsf(f), 1e-8f));
        d += (f != 0.f) ? s : 0.f;
    }
    float inv = 1.f / (d + 1e-7f);
    e_s[t] = inv * a;
    __syncthreads();

    // pass 2: write adj rows coalesced (row = y, col = t), accumulate h[t]
    float hacc = 0.f;
    float* arow = adj + (size_t)bc * (256 * 256);
    #pragma unroll 4
    for (int y = 0; y < 256; y++) {
        float f = a * v_s[y] + a_s[y] * v;        // = g[t,y] = g[y,t]
        float s = sqrtf(fmaxf(fabsf(f), 1e-8f));
        float g = (f > 0.f) ? s : ((f < 0.f) ? -s : 0.f);
        arow[y * 256 + t] = g * inv;              // adj[y][t] = g[y,t]*inv_d[t]
        hacc += g * e_s[y];                       // h[t] += g[t,y]*inv_d[y]*a[y]
    }
    h[bc*Ff + t] = hacc;
}

// ---------------------------------------------------------------------------
// K3: out[b,o] = sum_k Z[b,k]*W[o,k], Z = [h | x] (B x 2048), W (2048 x 2048)
// fp32 SIMT GEMM: 64x64 block tile, BK=16, 256 threads, 4x4 microtile
// ---------------------------------------------------------------------------
#define BM 64
#define BN 64
#define BK 16
__global__ __launch_bounds__(256) void k_gemm(
    const float* __restrict__ h, const float* __restrict__ x,
    const float* __restrict__ W, float* __restrict__ out)
{
    __shared__ float As[BK][BM + 4];
    __shared__ float Bs[BK][BN + 4];

    int tid = threadIdx.x;
    int bn = blockIdx.x * BN;
    int bm = blockIdx.y * BM;
    int tm = (tid / 16) * 4;
    int tn = (tid % 16) * 4;

    int lr = tid / 4;         // 0..63
    int lk = (tid % 4) * 4;   // 0,4,8,12

    float acc[4][4] = {};

    for (int k0 = 0; k0 < 2048; k0 += BK) {
        const float* Zb = (k0 < 1024) ? h : x;
        int koff = (k0 < 1024) ? k0 : (k0 - 1024);
        float4 av = *(const float4*)(Zb + (size_t)(bm + lr) * 1024 + koff + lk);
        float4 bv = *(const float4*)(W  + (size_t)(bn + lr) * 2048 + k0   + lk);
        As[lk+0][lr] = av.x; As[lk+1][lr] = av.y; As[lk+2][lr] = av.z; As[lk+3][lr] = av.w;
        Bs[lk+0][lr] = bv.x; Bs[lk+1][lr] = bv.y; Bs[lk+2][lr] = bv.z; Bs[lk+3][lr] = bv.w;
        __syncthreads();
        #pragma unroll
        for (int kk = 0; kk < BK; kk++) {
            float ar[4], br[4];
            #pragma unroll
            for (int i = 0; i < 4; i++) ar[i] = As[kk][tm + i];
            #pragma unroll
            for (int j = 0; j < 4; j++) br[j] = Bs[kk][tn + j];
            #pragma unroll
            for (int i = 0; i < 4; i++)
                #pragma unroll
                for (int j = 0; j < 4; j++)
                    acc[i][j] = fmaf(ar[i], br[j], acc[i][j]);
        }
        __syncthreads();
    }
    #pragma unroll
    for (int i = 0; i < 4; i++)
        #pragma unroll
        for (int j = 0; j < 4; j++)
            out[(size_t)(bm + tm + i) * 2048 + (bn + tn + j)] = acc[i][j];
}

// ---------------------------------------------------------------------------
extern "C" void kernel_launch(void* const* d_in, const int* in_sizes, int n_in,
                              void* d_out, int out_size)
{
    const float* x    = (const float*)d_in[0];  // (256,4,256)
    const float* nbr  = (const float*)d_in[1];  // (256,64,4,256)
    const float* Wa1  = (const float*)d_in[2];  // (4,256)
    const float* Wa2  = (const float*)d_in[3];  // (4,256)
    const float* Wc   = (const float*)d_in[4];  // (2048,8,256) -> (2048,2048)

    float* out = (float*)d_out;                 // first 256*8*256 = 524288: out
    float* adj = out + 256 * 8 * 256;           // then (256,4,256,256): adj

    float* nbw;  cudaGetSymbolAddress((void**)&nbw, g_nbw);
    float* hbuf; cudaGetSymbolAddress((void**)&hbuf, g_h);

    k_attn<<<256, 256>>>(x, nbr, Wa1, Wa2, nbw);
    k_adj<<<1024, 256>>>(x, nbw, adj, hbuf);
    dim3 g3(2048 / BN, 256 / BM);
    k_gemm<<<g3, 256>>>(hbuf, x, Wc, out);
    (void)in_sizes; (void)n_in; (void)out_size;
}

// round 2
// speedup vs baseline: 1.6597x; 1.6597x over previous
#include <cuda_runtime.h>
#include <math.h>

#define Bsz 256
#define Cc  4
#define Nn  64
#define Ff  256

// Scratch (static device arrays; allocation-free rule)
__device__ float g_nbw[Bsz * Cc * Ff];          // 1 MB
__device__ float g_zt[2048 * 256];              // 2 MB: Z^T  (k-major: [k][b])
__device__ float g_wt[2048 * 2048];             // 16 MB: W^T (k-major: [k][o])

// ---------------------------------------------------------------------------
// f32x2 helpers (Blackwell packed fp32; 2x FFMA throughput)
// ---------------------------------------------------------------------------
__device__ __forceinline__ unsigned long long dup2(float x) {
    unsigned long long r;
    asm("mov.b64 %0, {%1, %1};" : "=l"(r) : "f"(x));
    return r;
}
__device__ __forceinline__ void ffma2(unsigned long long& d,
                                      unsigned long long a,
                                      unsigned long long b) {
    asm("fma.rn.f32x2 %0, %1, %2, %0;" : "+l"(d) : "l"(a), "l"(b));
}
__device__ __forceinline__ float2 unpk2(unsigned long long v) {
    float2 f;
    asm("mov.b64 {%0, %1}, %2;" : "=f"(f.x), "=f"(f.y) : "l"(v));
    return f;
}

// ---------------------------------------------------------------------------
// K1: attention (s1, s2, softmax w), nbw[b,c,f] = sum_n w[n]*nbr[b,n,c,f],
//     and scatter x into the k-major Zt (rows 1024..2047).
// grid = 256 (one block per b), 256 threads
// ---------------------------------------------------------------------------
__global__ __launch_bounds__(256) void k_attn(
    const float* __restrict__ x, const float* __restrict__ nbr,
    const float* __restrict__ Wa1, const float* __restrict__ Wa2,
    float* __restrict__ nbw, float* __restrict__ zt)
{
    int b = blockIdx.x;
    int t = threadIdx.x;
    __shared__ float w2s_s[256];
    __shared__ float red[256];
    __shared__ float s2_s[64];
    __shared__ float w_s[64];
    __shared__ float s1_s;

    float x0 = x[(b*Cc+0)*Ff+t], x1 = x[(b*Cc+1)*Ff+t];
    float x2 = x[(b*Cc+2)*Ff+t], x3 = x[(b*Cc+3)*Ff+t];
    // scatter x into Zt rows 1024 + c*256 + t, col b
    zt[(1024 + 0*Ff + t)*256 + b] = x0;
    zt[(1024 + 1*Ff + t)*256 + b] = x1;
    zt[(1024 + 2*Ff + t)*256 + b] = x2;
    zt[(1024 + 3*Ff + t)*256 + b] = x3;

    float xs  = x0 + x1 + x2 + x3;
    float w1s = Wa1[t] + Wa1[256+t] + Wa1[512+t] + Wa1[768+t];
    float w2s = Wa2[t] + Wa2[256+t] + Wa2[512+t] + Wa2[768+t];
    w2s_s[t] = w2s;
    red[t]   = xs * w1s;
    __syncthreads();
    for (int off = 128; off > 0; off >>= 1) {
        if (t < off) red[t] += red[t + off];
        __syncthreads();
    }
    if (t == 0) s1_s = red[0];

    // s2[n]: 8 warps x 8 n each, float4 loads
    int warp = t >> 5, lane = t & 31;
    const float* nb_b = nbr + (size_t)b * Nn * Cc * Ff;
    for (int n = warp; n < Nn; n += 8) {
        const float4* p4 = (const float4*)(nb_b + (size_t)n * (Cc * Ff));
        float acc = 0.f;
        #pragma unroll
        for (int j = lane; j < 256; j += 32) {
            float4 v = p4[j];
            float4 w = *(const float4*)&w2s_s[(4*j) & 255];
            acc += v.x*w.x + v.y*w.y + v.z*w.z + v.w*w.w;
        }
        #pragma unroll
        for (int o = 16; o > 0; o >>= 1) acc += __shfl_down_sync(0xffffffffu, acc, o);
        if (lane == 0) s2_s[n] = acc;
    }
    __syncthreads();

    if (t == 0) {
        float s1 = s1_s;
        float m = -1e30f;
        for (int n = 0; n < Nn; n++) {
            float v = s1 * s2_s[n];
            s2_s[n] = v;
            m = fmaxf(m, v);
        }
        float sum = 0.f;
        for (int n = 0; n < Nn; n++) {
            float e = expf(s2_s[n] - m);
            w_s[n] = e;
            sum += e;
        }
        float isum = 1.f / sum;
        for (int n = 0; n < Nn; n++) w_s[n] *= isum;
    }
    __syncthreads();

    // nbw: thread -> (c = t/64, 4-wide f group), float4, unrolled over n
    {
        int c  = t >> 6;
        int fg = (t & 63) << 2;
        const float* base = nb_b + c * Ff + fg;
        float4 acc = make_float4(0.f, 0.f, 0.f, 0.f);
        #pragma unroll 8
        for (int n = 0; n < Nn; n++) {
            float4 v = *(const float4*)(base + (size_t)n * (Cc * Ff));
            float w = w_s[n];
            acc.x += w*v.x; acc.y += w*v.y; acc.z += w*v.z; acc.w += w*v.w;
        }
        *(float4*)&nbw[(b*Cc + c)*Ff + fg] = acc;
    }
}

// ---------------------------------------------------------------------------
// K2: per (b,c) 256x256 adj tile + h (written transposed into Zt).
//   g[x,y] = f * rsqrt(max(|f|,1e-8)),  f = a[x]*v[y] + a[y]*v[x]  (symmetric)
//   D[y] = sum_x |g[x,y]| (== row sum);  adj[x,y] = g[x,y]/(D[y]+1e-7)
//   h[x] = sum_y g[x,y] * (a[y]/(D[y]+1e-7))
// grid = 1024 (b*4+c), 256 threads: thread = (y-quadrant yq, column group cg)
// ---------------------------------------------------------------------------
__global__ __launch_bounds__(256) void k_adj(
    const float* __restrict__ x, const float* __restrict__ nbw,
    float* __restrict__ adj, float* __restrict__ zt)
{
    int bc = blockIdx.x;
    int b  = bc >> 2, c = bc & 3;
    int t  = threadIdx.x;
    __shared__ float a_s[256];
    __shared__ float v_s[256];
    __shared__ float inv_s[256];
    __shared__ float e_s[256];
    __shared__ float part[4][256];

    a_s[t] = x[bc*Ff + t];
    v_s[t] = nbw[bc*Ff + t];
    __syncthreads();

    int yq = t >> 6;
    int cg = (t & 63) << 2;
    float4 ac = *(float4*)&a_s[cg];
    float4 vc = *(float4*)&v_s[cg];
    int y0 = yq * 64, y1 = y0 + 64;

    // pass 1: partial column sums of |g|
    float4 dp = make_float4(0.f, 0.f, 0.f, 0.f);
    #pragma unroll 4
    for (int y = y0; y < y1; y++) {
        float ay = a_s[y], vy = v_s[y];
        float f0 = ac.x*vy + ay*vc.x;
        float f1 = ac.y*vy + ay*vc.y;
        float f2 = ac.z*vy + ay*vc.z;
        float f3 = ac.w*vy + ay*vc.w;
        float af0 = fabsf(f0), af1 = fabsf(f1), af2 = fabsf(f2), af3 = fabsf(f3);
        float r0 = rsqrtf(fmaxf(af0, 1e-8f));
        float r1 = rsqrtf(fmaxf(af1, 1e-8f));
        float r2 = rsqrtf(fmaxf(af2, 1e-8f));
        float r3 = rsqrtf(fmaxf(af3, 1e-8f));
        dp.x += af0*r0; dp.y += af1*r1; dp.z += af2*r2; dp.w += af3*r3;
    }
    *(float4*)&part[yq][cg] = dp;
    __syncthreads();

    float d = part[0][t] + part[1][t] + part[2][t] + part[3][t];
    float inv = 1.f / (d + 1e-7f);
    inv_s[t] = inv;
    e_s[t]   = inv * a_s[t];
    __syncthreads();

    float4 invc = *(float4*)&inv_s[cg];
    float4 hp = make_float4(0.f, 0.f, 0.f, 0.f);
    float* arow = adj + (size_t)bc * 65536;
    #pragma unroll 4
    for (int y = y0; y < y1; y++) {
        float ay = a_s[y], vy = v_s[y], ey = e_s[y];
        float f0 = ac.x*vy + ay*vc.x;
        float f1 = ac.y*vy + ay*vc.y;
        float f2 = ac.z*vy + ay*vc.z;
        float f3 = ac.w*vy + ay*vc.w;
        float g0 = f0 * rsqrtf(fmaxf(fabsf(f0), 1e-8f));
        float g1 = f1 * rsqrtf(fmaxf(fabsf(f1), 1e-8f));
        float g2 = f2 * rsqrtf(fmaxf(fabsf(f2), 1e-8f));
        float g3 = f3 * rsqrtf(fmaxf(fabsf(f3), 1e-8f));
        float4 o = make_float4(g0*invc.x, g1*invc.y, g2*invc.z, g3*invc.w);
        __stcs((float4*)&arow[y*256 + cg], o);
        hp.x += g0*ey; hp.y += g1*ey; hp.z += g2*ey; hp.w += g3*ey;
    }
    __syncthreads();   // part[] reads from pass 1 are long done
    *(float4*)&part[yq][cg] = hp;
    __syncthreads();
    float h = part[0][t] + part[1][t] + part[2][t] + part[3][t];
    zt[(c*Ff + t)*256 + b] = h;     // h^T into Zt rows 0..1023
}

// ---------------------------------------------------------------------------
// K_wt: W (2048x2048, o-major) -> Wt (k-major). Tiled 32x32 transpose.
// ---------------------------------------------------------------------------
__global__ __launch_bounds__(256) void k_wt(
    const float* __restrict__ W, float* __restrict__ Wt)
{
    __shared__ float tl[32][33];
    int tx = threadIdx.x, ty = threadIdx.y;
    int bx = blockIdx.x * 32;   // k
    int by = blockIdx.y * 32;   // o
    #pragma unroll
    for (int j = 0; j < 32; j += 8)
        tl[ty + j][tx] = W[(size_t)(by + ty + j) * 2048 + bx + tx];
    __syncthreads();
    #pragma unroll
    for (int j = 0; j < 32; j += 8)
        Wt[(size_t)(bx + ty + j) * 2048 + by + tx] = tl[tx][ty + j];
}

// ---------------------------------------------------------------------------
// K3: out[b,o] = sum_k Zt[k][b] * Wt[k][o]
// 64x64 tile, BK=16, 256 threads, 4m x 4n microtile via packed f32x2 FFMA2.
// grid = (2048/64, 256/64) = (32, 4) = 128 blocks
// ---------------------------------------------------------------------------
__global__ __launch_bounds__(256) void k_gemm(
    const float* __restrict__ Zt, const float* __restrict__ Wt,
    float* __restrict__ out)
{
    __shared__ __align__(16) float As[2][16][64];
    __shared__ __align__(16) float Bs[2][16][64];

    int tid = threadIdx.x;
    int bn = blockIdx.x * 64;
    int bm = blockIdx.y * 64;
    int lk = tid >> 4;            // 0..15 (k row for loads)
    int lg = (tid & 15) << 2;     // 0..60 (4-wide group for loads)
    int tm = (tid & 15) << 2;     // microtile m base
    int tn = (tid >> 4) << 2;     // microtile n base

    const float* Ap = Zt + (size_t)lk * 256  + bm + lg;
    const float* Bp = Wt + (size_t)lk * 2048 + bn + lg;

    float4 ra = *(const float4*)Ap;
    float4 rb = *(const float4*)Bp;
    *(float4*)&As[0][lk][lg] = ra;
    *(float4*)&Bs[0][lk][lg] = rb;
    __syncthreads();

    unsigned long long acc[2][4] = {};
    int buf = 0;

    for (int k0 = 0; k0 < 2048; k0 += 16) {
        bool last = (k0 + 16 >= 2048);
        if (!last) {
            ra = *(const float4*)(Ap + (size_t)(k0 + 16) * 256);
            rb = *(const float4*)(Bp + (size_t)(k0 + 16) * 2048);
        }
        #pragma unroll
        for (int kk = 0; kk < 16; kk++) {
            double2 a2 = *(double2*)&As[buf][kk][tm];
            float4  b4 = *(float4*)&Bs[buf][kk][tn];
            unsigned long long am0 = __double_as_longlong(a2.x);
            unsigned long long am1 = __double_as_longlong(a2.y);
            unsigned long long bd0 = dup2(b4.x);
            unsigned long long bd1 = dup2(b4.y);
            unsigned long long bd2 = dup2(b4.z);
            unsigned long long bd3 = dup2(b4.w);
            ffma2(acc[0][0], am0, bd0); ffma2(acc[0][1], am0, bd1);
            ffma2(acc[0][2], am0, bd2); ffma2(acc[0][3], am0, bd3);
            ffma2(acc[1][0], am1, bd0); ffma2(acc[1][1], am1, bd1);
            ffma2(acc[1][2], am1, bd2); ffma2(acc[1][3], am1, bd3);
        }
        if (!last) {
            *(float4*)&As[buf ^ 1][lk][lg] = ra;
            *(float4*)&Bs[buf ^ 1][lk][lg] = rb;
            __syncthreads();
            buf ^= 1;
        }
    }

    #pragma unroll
    for (int mp = 0; mp < 2; mp++) {
        #pragma unroll
        for (int j = 0; j < 4; j++) {
            float2 v = unpk2(acc[mp][j]);
            out[(size_t)(bm + tm + 2*mp    ) * 2048 + bn + tn + j] = v.x;
            out[(size_t)(bm + tm + 2*mp + 1) * 2048 + bn + tn + j] = v.y;
        }
    }
}

// ---------------------------------------------------------------------------
extern "C" void kernel_launch(void* const* d_in, const int* in_sizes, int n_in,
                              void* d_out, int out_size)
{
    const float* x    = (const float*)d_in[0];  // (256,4,256)
    const float* nbr  = (const float*)d_in[1];  // (256,64,4,256)
    const float* Wa1  = (const float*)d_in[2];  // (4,256)
    const float* Wa2  = (const float*)d_in[3];  // (4,256)
    const float* Wc   = (const float*)d_in[4];  // (2048,8,256) == (2048,2048)

    float* out = (float*)d_out;                 // (256,8,256) = 524288 floats
    float* adj = out + 256 * 8 * 256;           // (256,4,256,256)

    float* nbw; cudaGetSymbolAddress((void**)&nbw, g_nbw);
    float* zt;  cudaGetSymbolAddress((void**)&zt,  g_zt);
    float* wt;  cudaGetSymbolAddress((void**)&wt,  g_wt);

    dim3 tb(32, 8);
    k_wt<<<dim3(64, 64), tb>>>(Wc, wt);
    k_attn<<<256, 256>>>(x, nbr, Wa1, Wa2, nbw, zt);
    k_adj<<<1024, 256>>>(x, nbw, adj, zt);
    k_gemm<<<dim3(32, 4), 256>>>(zt, wt, out);
    (void)in_sizes; (void)n_in; (void)out_size;
}